// round 16
// baseline (speedup 1.0000x reference)
#include <cuda_runtime.h>
#include <cuda_bf16.h>
#include <cuda_fp16.h>
#include <cstdint>
#include <cfloat>
#include <math.h>

#define NTOK 8192
#define DIMM 512
#define DEPTH 6
#define HEADS 8
#define DH 64
#define WSZ 256
#define INNER 512
#define FF 1365
#define FF2 2730
#define FFPAD 1408
#define FF2SCR 2816

// per-layer weight buffer layout (elements)
#define WOFF_QKV 0
#define WOFF_WO  786432            // 1536*512
#define WOFF_W1  1048576           // + 512*512
#define WOFF_W2  2490368           // + 2816*512
#define WLSTRIDE 3211264           // + 512*1408

// ---------------------------------------------------------------------------
// Scratch (device globals; allocation is banned)
// ---------------------------------------------------------------------------
__device__ __align__(256) float g_x[NTOK * DIMM];
__device__ __align__(256) float g_pb1[DEPTH * FF2SCR];
__device__ __align__(256) float4 g_rot[NTOK * 32];      // {c*xs, s*xs, c/xs, s/xs}
__device__ __align__(256) __half g_af[NTOK * 512];
__device__ __align__(256) __half g_a2f[NTOK * 512];
__device__ __align__(256) __half g_gf[(size_t)NTOK * FFPAD];
__device__ __align__(256) __half g_wbf[(size_t)DEPTH * WLSTRIDE];
__device__ __align__(256) __nv_bfloat16 g_qh[NTOK * 512], g_ql[NTOK * 512];
__device__ __align__(256) __nv_bfloat16 g_kh[NTOK * 512], g_kl[NTOK * 512];
__device__ __align__(256) __half g_vtf[512 * NTOK];     // v [hd][tok] fp16

__device__ __forceinline__ uint32_t smem_to_u32(const void* p) {
    uint32_t a;
    asm("{ .reg .u64 t; cvta.to.shared.u64 t, %1; cvt.u32.u64 %0, t; }" : "=r"(a) : "l"(p));
    return a;
}
__device__ __forceinline__ void cpasync16(uint32_t dst, const void* src) {
    asm volatile("cp.async.cg.shared.global [%0], [%1], 16;" :: "r"(dst), "l"(src) : "memory");
}
#define CP_COMMIT() asm volatile("cp.async.commit_group;" ::: "memory")
#define CP_WAIT(n) asm volatile("cp.async.wait_group %0;" :: "n"(n) : "memory")
#define GRID_DEP_SYNC() asm volatile("griddepcontrol.wait;" ::: "memory")
#define GRID_DEP_TRIGGER() asm volatile("griddepcontrol.launch_dependents;" ::: "memory")

__device__ __forceinline__ uint32_t swz(int r, int chunk) {
    int pr = r >> 1;
    int cc = ((r & 1) << 2) | chunk;
    cc ^= (pr & 7);
    return (uint32_t)(pr * 128 + cc * 16);
}
__device__ __forceinline__ uint32_t swz64(int r, int c) {
    return (uint32_t)(r * 128 + ((c ^ (r & 7)) * 16));
}

__device__ __forceinline__ void ldx4(uint32_t& d0, uint32_t& d1, uint32_t& d2, uint32_t& d3,
                                     uint32_t addr) {
    asm volatile("ldmatrix.sync.aligned.m8n8.x4.shared.b16 {%0,%1,%2,%3}, [%4];"
                 : "=r"(d0), "=r"(d1), "=r"(d2), "=r"(d3) : "r"(addr));
}
__device__ __forceinline__ void mma16816(float* c, uint32_t a0, uint32_t a1, uint32_t a2,
                                         uint32_t a3, uint32_t b0, uint32_t b1) {
    asm volatile(
        "mma.sync.aligned.m16n8k16.row.col.f32.bf16.bf16.f32 "
        "{%0,%1,%2,%3}, {%4,%5,%6,%7}, {%8,%9}, {%0,%1,%2,%3};"
        : "+f"(c[0]), "+f"(c[1]), "+f"(c[2]), "+f"(c[3])
        : "r"(a0), "r"(a1), "r"(a2), "r"(a3), "r"(b0), "r"(b1));
}
__device__ __forceinline__ void mma16816h(float* c, uint32_t a0, uint32_t a1, uint32_t a2,
                                          uint32_t a3, uint32_t b0, uint32_t b1) {
    asm volatile(
        "mma.sync.aligned.m16n8k16.row.col.f32.f16.f16.f32 "
        "{%0,%1,%2,%3}, {%4,%5,%6,%7}, {%8,%9}, {%0,%1,%2,%3};"
        : "+f"(c[0]), "+f"(c[1]), "+f"(c[2]), "+f"(c[3])
        : "r"(a0), "r"(a1), "r"(a2), "r"(a3), "r"(b0), "r"(b1));
}
__device__ __forceinline__ uint32_t packh2(float a, float b) {
    __half2 h = __floats2half2_rn(a, b);
    return *reinterpret_cast<uint32_t*>(&h);
}

// ===========================================================================
// One-time rotary/xpos coefficient table: (pos, d<32) -> 4 floats.
// ===========================================================================
__global__ void rot_table_kernel()
{
    int idx = blockIdx.x * 256 + threadIdx.x;
    if (idx >= NTOK * 32) return;
    int pos = idx >> 5, d = idx & 31;
    float inv_freq = powf(10000.f, -(float)d / 32.f);
    float fr = (float)pos * inv_freq;
    float c = cosf(fr), s = sinf(fr);
    float sv = (2.f * (float)d + 0.4f * 64.f) / (1.4f * 64.f);
    float pw = ((float)pos - (float)(NTOK / 2)) / (float)(WSZ / 2);
    float xs = powf(sv, pw);
    g_rot[idx] = make_float4(c * xs, s * xs, c / xs, s / xs);
}

// ===========================================================================
// Conversion kernels
// ===========================================================================
__global__ void cvt_pad_A(const float* __restrict__ src, __half* __restrict__ h,
                          int Mr, int Kc, int Kp)
{
    int idx = blockIdx.x * 256 + threadIdx.x;
    if (idx >= Mr * Kp) return;
    int r = idx / Kp, c = idx - r * Kp;
    float v = (c < Kc) ? src[(size_t)r * Kc + c] : 0.f;
    h[idx] = __float2half_rn(v);
}

__global__ void cvt_pad_Bt(const float* __restrict__ src, __half* __restrict__ h,
                           int Kc, int Nc, int Kp, int Nscr, int srcStride, int gluPerm)
{
    __shared__ float t[32][33];
    int tk0 = blockIdx.x * 32;
    int tn0 = blockIdx.y * 32;
    int tx = threadIdx.x & 31;
    int ty = threadIdx.x >> 5;

    int nout = tn0 + tx;
    int ns; bool nok;
    if (gluPerm) {
        int p = nout >> 1;
        ns = (nout & 1) ? p + FF : p;
        nok = p < FF;
    } else {
        ns = nout;
        nok = nout < Nc;
    }
#pragma unroll
    for (int i = 0; i < 4; i++) {
        int k = tk0 + ty + 8 * i;
        float v = (k < Kc && nok) ? src[(size_t)k * srcStride + ns] : 0.f;
        t[ty + 8 * i][tx] = v;
    }
    __syncthreads();
#pragma unroll
    for (int i = 0; i < 4; i++) {
        int n = tn0 + ty + 8 * i, k = tk0 + tx;
        if (n < Nscr && k < Kp)
            h[(size_t)n * Kp + k] = __float2half_rn(t[tx][ty + 8 * i]);
    }
}

__global__ void permute_b1_kernel(const float* __restrict__ b1, float* __restrict__ dst)
{
    int n = blockIdx.x * 256 + threadIdx.x;
    if (n >= FF2SCR) return;
    int p = n >> 1;
    dst[n] = (p < FF) ? b1[(n & 1) ? p + FF : p] : 0.f;
}

// ===========================================================================
// fp16 single-term tensor-core GEMM with PDL, BK=64.
// Stage 32KB: A blk0@0, A blk1@8192, B blk0@16384, B blk1@24576.
// mode 0: fp32 C (+bias,+res) and optional fp16 plane Oh.
// mode 1: GLU epilogue -> fp16 plane Oh.
// mode 2: QKV epilogue -> qknorm+rotary -> g_qh/ql/kh/kl; v -> g_vtf.
// ===========================================================================
#define STAGE_BYTES 32768
#define NSTAGE 3
#define GEMM_SMEM (NSTAGE * STAGE_BYTES + 1024)

__global__ void __launch_bounds__(256, 2) fp16_gemm_kernel(
    const __half* __restrict__ A, const __half* __restrict__ B,
    const float* __restrict__ bias, const float* __restrict__ res,
    float* __restrict__ C, __half* __restrict__ Oh,
    const float* __restrict__ qsc, const float* __restrict__ ksc,
    int M, int N, int Kpad, int ostride, int mode)
{
    extern __shared__ char smraw[];
    char* sm = (char*)(((uintptr_t)smraw + 1023) & ~(uintptr_t)1023);
    uint32_t sb = smem_to_u32(sm);

    int tid = threadIdx.x, wid = tid >> 5, lane = tid & 31;
    int mw = wid >> 1, nw = wid & 1;
    int m0 = blockIdx.y * 128, n0 = blockIdx.x * 128;

    uint32_t aAddr[2], bAddr[4];
    {
        int t = lane >> 3, l7 = lane & 7;
#pragma unroll
        for (int mi = 0; mi < 2; mi++) {
            int r = mw * 32 + mi * 16 + ((t & 1) << 3) + l7;
            aAddr[mi] = sb + swz(r, t >> 1);
        }
#pragma unroll
        for (int j = 0; j < 4; j++) {
            int r = nw * 64 + j * 16 + ((t >> 1) << 3) + l7;
            bAddr[j] = sb + 16384 + swz(r, t & 1);
        }
    }

    float acc[2][8][4];
#pragma unroll
    for (int mi = 0; mi < 2; mi++)
#pragma unroll
        for (int j = 0; j < 8; j++)
#pragma unroll
            for (int q = 0; q < 4; q++) acc[mi][j][q] = 0.f;

    const int niter = Kpad / 64;
    int cr = tid >> 1;
    int c0 = (tid & 1) * 2;
    const __half* aSrc = A + (size_t)(m0 + cr) * Kpad + c0 * 8;
    const __half* bSrc = B + (size_t)(n0 + cr) * Kpad + c0 * 8;
    uint32_t dA0 = swz(cr, c0), dA1 = swz(cr, c0 + 1);

    // full stage: A blk0/blk1 (k0, k0+32), B blk0/blk1
#define ISSUE_STAGE(s, k0) do {                                           \
        uint32_t base = sb + (uint32_t)(s) * STAGE_BYTES;                 \
        cpasync16(base + dA0,         aSrc + (k0));                       \
        cpasync16(base + dA1,         aSrc + (k0) + 8);                   \
        cpasync16(base + 8192 + dA0,  aSrc + (k0) + 32);                  \
        cpasync16(base + 8192 + dA1,  aSrc + (k0) + 40);                  \
        cpasync16(base + 16384 + dA0, bSrc + (k0));                       \
        cpasync16(base + 16384 + dA1, bSrc + (k0) + 8);                   \
        cpasync16(base + 24576 + dA0, bSrc + (k0) + 32);                  \
        cpasync16(base + 24576 + dA1, bSrc + (k0) + 40);                  \
        CP_COMMIT();                                                      \
    } while (0)

    // ---- PDL prologue: B (weights) for stages 0,1 are predecessor-independent
    cpasync16(sb + 16384 + dA0, bSrc);
    cpasync16(sb + 16384 + dA1, bSrc + 8);
    cpasync16(sb + 24576 + dA0, bSrc + 32);
    cpasync16(sb + 24576 + dA1, bSrc + 40);
    cpasync16(sb + STAGE_BYTES + 16384 + dA0, bSrc + 64);
    cpasync16(sb + STAGE_BYTES + 16384 + dA1, bSrc + 72);
    cpasync16(sb + STAGE_BYTES + 24576 + dA0, bSrc + 96);
    cpasync16(sb + STAGE_BYTES + 24576 + dA1, bSrc + 104);
    GRID_DEP_SYNC();                 // wait for predecessor's output (A side)
    cpasync16(sb + dA0,        aSrc);
    cpasync16(sb + dA1,        aSrc + 8);
    cpasync16(sb + 8192 + dA0, aSrc + 32);
    cpasync16(sb + 8192 + dA1, aSrc + 40);
    CP_COMMIT();                     // G1 = {B s0, B s1, A s0}
    cpasync16(sb + STAGE_BYTES + dA0,        aSrc + 64);
    cpasync16(sb + STAGE_BYTES + dA1,        aSrc + 72);
    cpasync16(sb + STAGE_BYTES + 8192 + dA0, aSrc + 96);
    cpasync16(sb + STAGE_BYTES + 8192 + dA1, aSrc + 104);
    CP_COMMIT();                     // G2 = {A s1}

    for (int it = 0; it < niter; ++it) {
        int s = it % NSTAGE;
        if (it + 1 < niter) CP_WAIT(1); else CP_WAIT(0);
        __syncthreads();
        if (it + 2 < niter) ISSUE_STAGE((it + 2) % NSTAGE, (it + 2) * 64);

        uint32_t stage = (uint32_t)s * STAGE_BYTES;
#pragma unroll
        for (int ks = 0; ks < 4; ks++) {
            uint32_t blk = stage + (uint32_t)((ks >> 1) * 8192);
            uint32_t x = (uint32_t)((ks & 1) * 32);
            uint32_t ah[2][4], bh[4][4];
            ldx4(ah[0][0], ah[0][1], ah[0][2], ah[0][3], (aAddr[0] + blk) ^ x);
            ldx4(ah[1][0], ah[1][1], ah[1][2], ah[1][3], (aAddr[1] + blk) ^ x);
#pragma unroll
            for (int j = 0; j < 4; j++)
                ldx4(bh[j][0], bh[j][1], bh[j][2], bh[j][3], (bAddr[j] + blk) ^ x);
#pragma unroll
            for (int mi = 0; mi < 2; mi++)
#pragma unroll
                for (int j = 0; j < 4; j++) {
                    mma16816h(acc[mi][2 * j],     ah[mi][0], ah[mi][1], ah[mi][2], ah[mi][3], bh[j][0], bh[j][1]);
                    mma16816h(acc[mi][2 * j + 1], ah[mi][0], ah[mi][1], ah[mi][2], ah[mi][3], bh[j][2], bh[j][3]);
                }
        }
    }
#undef ISSUE_STAGE

    GRID_DEP_TRIGGER();              // successors may launch & prefetch weights

    int colq = (lane & 3) * 2;

    if (mode == 2) {
        int colbase = n0 + nw * 64;          // one head-segment per warp-half
        int region = n0 >> 9;                // CTA-uniform: 0=q, 1=k, 2=v
        if (region == 2) {
            // ---- V: transpose via smem stage, coalesced write to g_vtf ----
            __half* vs = (__half*)sm;        // [128 dims][136 toks] padded
            __syncthreads();                 // all warps done reading pipeline smem
#pragma unroll
            for (int mi = 0; mi < 2; mi++) {
#pragma unroll
                for (int half = 0; half < 2; half++) {
                    int rloc = mw * 32 + mi * 16 + (lane >> 2) + half * 8;  // token
#pragma unroll
                    for (int j = 0; j < 8; j++) {
                        int cloc = nw * 64 + j * 8 + colq;                  // v-dim
                        vs[(size_t)cloc * 136 + rloc] = __float2half_rn(acc[mi][j][half * 2]);
                        vs[(size_t)(cloc + 1) * 136 + rloc] = __float2half_rn(acc[mi][j][half * 2 + 1]);
                    }
                }
            }
            __syncthreads();
            int hdl = tid >> 1;              // local dim row 0..127
            int tk0 = (tid & 1) * 64;        // token half
            __half* dst = g_vtf + (size_t)(n0 - 1024 + hdl) * NTOK + m0 + tk0;
            const __half* srcp = vs + (size_t)hdl * 136 + tk0;
#pragma unroll
            for (int i = 0; i < 8; i++)
                *(uint4*)(dst + i * 8) = *(const uint4*)(srcp + i * 8);
            return;
        }
        // ---- Q/K: qknorm + xpos rotary fused ----
#pragma unroll
        for (int mi = 0; mi < 2; mi++) {
#pragma unroll
            for (int half = 0; half < 2; half++) {
                int r = m0 + mw * 32 + mi * 16 + (lane >> 2) + half * 8;
                float ss = 0.f;
#pragma unroll
                for (int j = 0; j < 8; j++) {
                    float a = acc[mi][j][half * 2], b = acc[mi][j][half * 2 + 1];
                    ss += a * a + b * b;
                }
                ss += __shfl_xor_sync(0xFFFFFFFF, ss, 1);
                ss += __shfl_xor_sync(0xFFFFFFFF, ss, 2);
                float invn = 1.f / fmaxf(sqrtf(ss), 1e-12f);
                const float* sc = (region == 0) ? qsc : ksc;
                __nv_bfloat16* OH = (region == 0) ? g_qh : g_kh;
                __nv_bfloat16* OL = (region == 0) ? g_ql : g_kl;
                int cb = colbase - region * 512;
#pragma unroll
                for (int j = 0; j < 4; j++) {
                    int d0 = j * 8 + colq;
                    float4 t0 = g_rot[(size_t)r * 32 + d0];
                    float4 t1 = g_rot[(size_t)r * 32 + d0 + 1];
                    float cx0 = (region == 0) ? t0.x : t0.z;
                    float sx0 = (region == 0) ? t0.y : t0.w;
                    float cx1 = (region == 0) ? t1.x : t1.z;
                    float sx1 = (region == 0) ? t1.y : t1.w;
                    float v00 = acc[mi][j][half * 2]         * invn * sc[d0];
                    float v01 = acc[mi][j][half * 2 + 1]     * invn * sc[d0 + 1];
                    float w00 = acc[mi][j + 4][half * 2]     * invn * sc[d0 + 32];
                    float w01 = acc[mi][j + 4][half * 2 + 1] * invn * sc[d0 + 33];
                    float oA0 = v00 * cx0 - w00 * sx0;
                    float oA1 = v01 * cx1 - w01 * sx1;
                    float oB0 = w00 * cx0 + v00 * sx0;
                    float oB1 = w01 * cx1 + v01 * sx1;
                    size_t o1 = (size_t)r * 512 + cb + j * 8 + colq;
                    size_t o2 = o1 + 32;
                    __nv_bfloat162 h0 = __floats2bfloat162_rn(oA0, oA1);
                    float2 f0 = __bfloat1622float2(h0);
                    *(__nv_bfloat162*)(OH + o1) = h0;
                    *(__nv_bfloat162*)(OL + o1) = __floats2bfloat162_rn(oA0 - f0.x, oA1 - f0.y);
                    __nv_bfloat162 h1 = __floats2bfloat162_rn(oB0, oB1);
                    float2 f1 = __bfloat1622float2(h1);
                    *(__nv_bfloat162*)(OH + o2) = h1;
                    *(__nv_bfloat162*)(OL + o2) = __floats2bfloat162_rn(oB0 - f1.x, oB1 - f1.y);
                }
            }
        }
        return;
    }

#pragma unroll
    for (int mi = 0; mi < 2; mi++) {
        int rbase = m0 + mw * 32 + mi * 16 + (lane >> 2);
#pragma unroll
        for (int j = 0; j < 8; j++) {
            int col = n0 + nw * 64 + j * 8 + colq;
            if (col < N) {
                float bx = 0.f, by = 0.f;
                if (bias) { bx = bias[col]; by = bias[col + 1]; }
                if (mode == 1) {
                    int p = col >> 1;
#pragma unroll
                    for (int half = 0; half < 2; half++) {
                        int r = rbase + half * 8;
                        float a = acc[mi][j][half * 2] + bx;
                        float g = acc[mi][j][half * 2 + 1] + by;
                        float v = a * 0.5f * g * (1.f + erff(g * 0.70710678118654752f));
                        Oh[(size_t)r * ostride + p] = __float2half_rn(v);
                    }
                } else {
#pragma unroll
                    for (int half = 0; half < 2; half++) {
                        int r = rbase + half * 8;
                        size_t o = (size_t)r * N + col;
                        float v0 = acc[mi][j][half * 2] + bx;
                        float v1 = acc[mi][j][half * 2 + 1] + by;
                        if (res) { v0 += res[o]; v1 += res[o + 1]; }
                        *(float2*)(C + o) = make_float2(v0, v1);
                        if (Oh) {
                            __half2 hv = __floats2half2_rn(v0, v1);
                            *(__half2*)(Oh + (size_t)r * ostride + col) = hv;
                        }
                    }
                }
            }
        }
    }
}

// ===========================================================================
// Tensor-core flash attention (R12 validated) with PDL wrap.
// ===========================================================================
#define ATT_STAGE 24576
#define ATT_SMEM (32768 + 2 * ATT_STAGE + 1024)

__global__ void __launch_bounds__(256) flash_attn_kernel()
{
    extern __shared__ char smraw[];
    char* sm = (char*)(((uintptr_t)smraw + 1023) & ~(uintptr_t)1023);
    uint32_t sb = smem_to_u32(sm);

    int tid = threadIdx.x, wid = tid >> 5, lane = tid & 31;
    int qb = blockIdx.x;
    int h = blockIdx.y;
    int start = (qb - 2) * 128;
    int cBeg = (start < 0) ? (-start) / 64 : 0;

    GRID_DEP_SYNC();   // all loads depend on the QKV GEMM's output

#define LOAD_CHUNK(sidx, kb_) do {                                                     \
        uint32_t base_ = sb + 32768 + (uint32_t)(sidx) * ATT_STAGE;                    \
        _Pragma("unroll")                                                              \
        for (int i_ = 0; i_ < 2; i_++) {                                               \
            int slot_ = tid * 2 + i_;                                                  \
            int row_ = slot_ >> 3, ch_ = slot_ & 7;                                    \
            uint32_t d_ = swz64(row_, ch_);                                            \
            cpasync16(base_ + d_,         g_kh + (size_t)((kb_) + row_) * 512 + h * 64 + ch_ * 8); \
            cpasync16(base_ + 8192 + d_,  g_kl + (size_t)((kb_) + row_) * 512 + h * 64 + ch_ * 8); \
            cpasync16(base_ + 16384 + d_, g_vtf + (size_t)(h * 64 + row_) * NTOK + (kb_) + ch_ * 8); \
        }                                                                              \
        CP_COMMIT();                                                                   \
    } while (0)

    {
#pragma unroll
        for (int i = 0; i < 4; i++) {
            int slot = tid * 4 + i;
            int row = slot >> 3, ch = slot & 7;
            uint32_t d = swz64(row, ch);
            const __nv_bfloat16* sh = g_qh + (size_t)(qb * 128 + row) * 512 + h * 64 + ch * 8;
            const __nv_bfloat16* slo = g_ql + (size_t)(qb * 128 + row) * 512 + h * 64 + ch * 8;
            cpasync16(sb + d, sh);
            cpasync16(sb + 16384 + d, slo);
        }
        LOAD_CHUNK(0, start + cBeg * 64);
        if (cBeg + 1 <= 5) LOAD_CHUNK(1, start + (cBeg + 1) * 64);
    }

    int t = lane >> 3, l7 = lane & 7;
    uint32_t aOff = swz64(wid * 16 + ((t & 1) << 3) + l7, t >> 1);
    uint32_t bOff[4];
#pragma unroll
    for (int j = 0; j < 4; j++)
        bOff[j] = swz64(j * 16 + ((t >> 1) << 3) + l7, t & 1);

    uint32_t qfh[4][4], qfl[4][4];
    float o4[8][4];
#pragma unroll
    for (int j = 0; j < 8; j++)
#pragma unroll
        for (int q = 0; q < 4; q++) o4[j][q] = 0.f;
    float m0 = -16.f, m1 = -16.f, l0 = 0.f, l1 = 0.f;

    int r0 = qb * 128 + wid * 16 + (lane >> 2);
    int colq = (lane & 3) * 2;
    int tqmin = qb * 128 + wid * 16;

    for (int c = cBeg; c <= 5; c++) {
        int s = (c - cBeg) & 1;
        int kb = start + c * 64;
        if (c < 5) CP_WAIT(1); else CP_WAIT(0);
        __syncthreads();

        if (c == cBeg) {
#pragma unroll
            for (int ks = 0; ks < 4; ks++) {
                uint32_t x = (uint32_t)(ks * 32);
                ldx4(qfh[ks][0], qfh[ks][1], qfh[ks][2], qfh[ks][3], (sb + aOff) ^ x);
                ldx4(qfl[ks][0], qfl[ks][1], qfl[ks][2], qfl[ks][3], (sb + 16384 + aOff) ^ x);
            }
        }

        bool active = ((tqmin + 15 - kb) >= 0) && ((tqmin - (kb + 63)) <= WSZ);
        if (active) {
            uint32_t kvb = sb + 32768 + (uint32_t)s * ATT_STAGE;

            float s4[8][4];
#pragma unroll
            for (int j = 0; j < 8; j++)
#pragma unroll
                for (int q = 0; q < 4; q++) s4[j][q] = 0.f;

#pragma unroll
            for (int ks = 0; ks < 4; ks++) {
                uint32_t x = (uint32_t)(ks * 32);
                uint32_t bh[4][4], bl[4][4];
#pragma unroll
                for (int j = 0; j < 4; j++) {
                    ldx4(bh[j][0], bh[j][1], bh[j][2], bh[j][3], (kvb + bOff[j]) ^ x);
                    ldx4(bl[j][0], bl[j][1], bl[j][2], bl[j][3], (kvb + 8192 + bOff[j]) ^ x);
                }
#pragma unroll
                for (int j = 0; j < 4; j++) {
                    mma16816(s4[2 * j],     qfh[ks][0], qfh[ks][1], qfh[ks][2], qfh[ks][3], bh[j][0], bh[j][1]);
                    mma16816(s4[2 * j + 1], qfh[ks][0], qfh[ks][1], qfh[ks][2], qfh[ks][3], bh[j][2], bh[j][3]);
                    mma16816(s4[2 * j],     qfh[ks][0], qfh[ks][1], qfh[ks][2], qfh[ks][3], bl[j][0], bl[j][1]);
                    mma16816(s4[2 * j + 1], qfh[ks][0], qfh[ks][1], qfh[ks][2], qfh[ks][3], bl[j][2], bl[j][3]);
                    mma16816(s4[2 * j],     qfl[ks][0], qfl[ks][1], qfl[ks][2], qfl[ks][3], bh[j][0], bh[j][1]);
                    mma16816(s4[2 * j + 1], qfl[ks][0], qfl[ks][1], qfl[ks][2], qfl[ks][3], bh[j][2], bh[j][3]);
                }
            }

#pragma unroll
            for (int j = 0; j < 8; j++) {
                int tkb = kb + j * 8 + colq;
#pragma unroll
                for (int q = 0; q < 4; q++) {
                    int tq = r0 + ((q >> 1) << 3);
                    int tk = tkb + (q & 1);
                    int diff = tq - tk;
                    s4[j][q] = (diff >= 0 && diff <= WSZ) ? s4[j][q] * 8.0f : -1e30f;
                }
            }
            float mx0 = -1e30f, mx1 = -1e30f;
#pragma unroll
            for (int j = 0; j < 8; j++) {
                mx0 = fmaxf(mx0, fmaxf(s4[j][0], s4[j][1]));
                mx1 = fmaxf(mx1, fmaxf(s4[j][2], s4[j][3]));
            }
            mx0 = fmaxf(mx0, __shfl_xor_sync(0xFFFFFFFF, mx0, 1));
            mx0 = fmaxf(mx0, __shfl_xor_sync(0xFFFFFFFF, mx0, 2));
            mx1 = fmaxf(mx1, __shfl_xor_sync(0xFFFFFFFF, mx1, 1));
            mx1 = fmaxf(mx1, __shfl_xor_sync(0xFFFFFFFF, mx1, 2));
            float mn0 = fmaxf(m0, mx0), mn1 = fmaxf(m1, mx1);
            float sc0 = __expf(m0 - mn0), sc1 = __expf(m1 - mn1);
            l0 *= sc0; l1 *= sc1;
#pragma unroll
            for (int j = 0; j < 8; j++) {
                o4[j][0] *= sc0; o4[j][1] *= sc0;
                o4[j][2] *= sc1; o4[j][3] *= sc1;
            }
            m0 = mn0; m1 = mn1;
#pragma unroll
            for (int j = 0; j < 8; j++) {
                float p0 = __expf(s4[j][0] - m0);
                float p1 = __expf(s4[j][1] - m0);
                float p2 = __expf(s4[j][2] - m1);
                float p3 = __expf(s4[j][3] - m1);
                l0 += p0 + p1; l1 += p2 + p3;
                s4[j][0] = p0; s4[j][1] = p1; s4[j][2] = p2; s4[j][3] = p3;
            }
            uint32_t pf[4][4];
#pragma unroll
            for (int ks = 0; ks < 4; ks++) {
                pf[ks][0] = packh2(s4[2 * ks][0],     s4[2 * ks][1]);
                pf[ks][1] = packh2(s4[2 * ks][2],     s4[2 * ks][3]);
                pf[ks][2] = packh2(s4[2 * ks + 1][0], s4[2 * ks + 1][1]);
                pf[ks][3] = packh2(s4[2 * ks + 1][2], s4[2 * ks + 1][3]);
            }
#pragma unroll
            for (int ks = 0; ks < 4; ks++) {
                uint32_t x = (uint32_t)(ks * 32);
                uint32_t vf[4][4];
#pragma unroll
                for (int j = 0; j < 4; j++)
                    ldx4(vf[j][0], vf[j][1], vf[j][2], vf[j][3], (kvb + 16384 + bOff[j]) ^ x);
#pragma unroll
                for (int j = 0; j < 4; j++) {
                    mma16816h(o4[2 * j],     pf[ks][0], pf[ks][1], pf[ks][2], pf[ks][3], vf[j][0], vf[j][1]);
                    mma16816h(o4[2 * j + 1], pf[ks][0], pf[ks][1], pf[ks][2], pf[ks][3], vf[j][2], vf[j][3]);
                }
            }
        }

        __syncthreads();
        if (c + 2 <= 5) LOAD_CHUNK(s, start + (c + 2) * 64);
    }
#undef LOAD_CHUNK

    GRID_DEP_TRIGGER();

    l0 += __shfl_xor_sync(0xFFFFFFFF, l0, 1);
    l0 += __shfl_xor_sync(0xFFFFFFFF, l0, 2);
    l1 += __shfl_xor_sync(0xFFFFFFFF, l1, 1);
    l1 += __shfl_xor_sync(0xFFFFFFFF, l1, 2);
    float il0 = 1.f / l0, il1 = 1.f / l1;

#pragma unroll
    for (int j = 0; j < 8; j++) {
        int col = h * 64 + j * 8 + colq;
        size_t off0 = (size_t)r0 * 512 + col;
        size_t off1 = (size_t)(r0 + 8) * 512 + col;
        *(__half2*)(g_af + off0) = __floats2half2_rn(o4[j][0] * il0, o4[j][1] * il0);
        *(__half2*)(g_af + off1) = __floats2half2_rn(o4[j][2] * il1, o4[j][3] * il1);
    }
}

// ---------------------------------------------------------------------------
extern "C" void kernel_launch(void* const* d_in, const int* in_sizes, int n_in,
                              void* d_out, int out_size)
{
    const float* x      = (const float*)d_in[0];
    const float* Wqkv   = (const float*)d_in[1];
    const float* Wo     = (const float*)d_in[2];
    const float* qscale = (const float*)d_in[3];
    const float* kscale = (const float*)d_in[4];
    const float* W1     = (const float*)d_in[5];
    const float* b1     = (const float*)d_in[6];
    const float* W2     = (const float*)d_in[7];
    const float* b2     = (const float*)d_in[8];

    float *px, *ppb1;
    __half *paf, *pa2f, *pgf, *pwbf;
    cudaGetSymbolAddress((void**)&px, g_x);
    cudaGetSymbolAddress((void**)&ppb1, g_pb1);
    cudaGetSymbolAddress((void**)&paf, g_af);
    cudaGetSymbolAddress((void**)&pa2f, g_a2f);
    cudaGetSymbolAddress((void**)&pgf, g_gf);
    cudaGetSymbolAddress((void**)&pwbf, g_wbf);

    cudaFuncSetAttribute(fp16_gemm_kernel,
                         cudaFuncAttributeMaxDynamicSharedMemorySize, GEMM_SMEM);
    cudaFuncSetAttribute(flash_attn_kernel,
                         cudaFuncAttributeMaxDynamicSharedMemorySize, ATT_SMEM);

    cudaStream_t s1;
    cudaStreamCreateWithFlags(&s1, cudaStreamNonBlocking);
    cudaEvent_t evFork, evWq[DEPTH], evW[DEPTH];
    cudaEventCreateWithFlags(&evFork, cudaEventDisableTiming);
    for (int l = 0; l < DEPTH; l++) {
        cudaEventCreateWithFlags(&evWq[l], cudaEventDisableTiming);
        cudaEventCreateWithFlags(&evW[l], cudaEventDisableTiming);
    }
    cudaEventRecord(evFork, 0);
    cudaStreamWaitEvent(s1, evFork, 0);

    // all layers' weight conversions upfront on the side stream
    for (int l = 0; l < DEPTH; l++) {
        __half* wf = pwbf + (size_t)l * WLSTRIDE;
        cvt_pad_Bt<<<dim3(16, 48), 256, 0, s1>>>(
            Wqkv + (size_t)l * DIMM * 3 * INNER, wf + WOFF_QKV,
            DIMM, 3 * INNER, 512, 1536, 3 * INNER, 0);
        cudaEventRecord(evWq[l], s1);
        cvt_pad_Bt<<<dim3(16, 16), 256, 0, s1>>>(
            Wo + (size_t)l * INNER * DIMM, wf + WOFF_WO,
            INNER, DIMM, 512, 512, DIMM, 0);
        cvt_pad_Bt<<<dim3(16, 88), 256, 0, s1>>>(
            W1 + (size_t)l * DIMM * FF2, wf + WOFF_W1,
            DIMM, FF2SCR, 512, FF2SCR, FF2, 1);
        permute_b1_kernel<<<(FF2SCR + 255) / 256, 256, 0, s1>>>(
            b1 + (size_t)l * FF2, ppb1 + (size_t)l * FF2SCR);
        cvt_pad_Bt<<<dim3(44, 16), 256, 0, s1>>>(
            W2 + (size_t)l * FF * DIMM, wf + WOFF_W2,
            FF, DIMM, FFPAD, 512, DIMM, 0);
        cudaEventRecord(evW[l], s1);
    }

    rot_table_kernel<<<(NTOK * 32 + 255) / 256, 256>>>();
    cvt_pad_A<<<(NTOK * 512 + 255) / 256, 256>>>(x, paf, NTOK, DIMM, 512);

    // PDL launch helpers
    cudaLaunchAttribute pdlAttr[1];
    pdlAttr[0].id = cudaLaunchAttributeProgrammaticStreamSerialization;
    pdlAttr[0].val.programmaticStreamSerializationAllowed = 1;

    auto launch_gemm = [&](dim3 grid, const __half* A, const __half* B,
                           const float* bias, const float* res, float* C,
                           __half* Oh, const float* qsc, const float* ksc,
                           int M, int N, int Kpad, int ostride, int mode) {
        cudaLaunchConfig_t cfg = {};
        cfg.gridDim = grid;
        cfg.blockDim = dim3(256, 1, 1);
        cfg.dynamicSmemBytes = GEMM_SMEM;
        cfg.stream = 0;
        cfg.attrs = pdlAttr;
        cfg.numAttrs = 1;
        cudaLaunchKernelEx(&cfg, fp16_gemm_kernel, A, B, bias, res, C, Oh,
                           qsc, ksc, M, N, Kpad, ostride, mode);
    };

    for (int lyr = 0; lyr < DEPTH; lyr++) {
        const float* xres = (lyr == 0) ? x : px;
        __half* wf = pwbf + (size_t)lyr * WLSTRIDE;

        // 1) QKV projection: fused qknorm+rotary epilogue + fused V transpose
        cudaStreamWaitEvent(0, evWq[lyr], 0);
        launch_gemm(dim3(12, 64), paf, wf + WOFF_QKV, nullptr, nullptr,
                    nullptr, nullptr, qscale + lyr * DH, kscale + lyr * DH,
                    NTOK, 3 * INNER, 512, 0, 2);

        // 2) flash attention -> g_af
        {
            cudaLaunchConfig_t cfg = {};
            cfg.gridDim = dim3(64, 8);
            cfg.blockDim = dim3(256, 1, 1);
            cfg.dynamicSmemBytes = ATT_SMEM;
            cfg.stream = 0;
            cfg.attrs = pdlAttr;
            cfg.numAttrs = 1;
            cudaLaunchKernelEx(&cfg, flash_attn_kernel);
        }

        // 3) output projection + residual; fp16 plane out
        cudaStreamWaitEvent(0, evW[lyr], 0);
        launch_gemm(dim3(4, 64), paf, wf + WOFF_WO, nullptr, xres,
                    px, pa2f, nullptr, nullptr, NTOK, DIMM, 512, DIMM, 0);

        // 4) FF up projection + b1 + fused GLU
        launch_gemm(dim3(22, 64), pa2f, wf + WOFF_W1,
                    ppb1 + (size_t)lyr * FF2SCR, nullptr, nullptr, pgf,
                    nullptr, nullptr, NTOK, FF2SCR, 512, FFPAD, 1);

        // 5) FF down projection + b2 + residual
        float* outp = (lyr == DEPTH - 1) ? (float*)d_out : px;
        __half* oh = (lyr == DEPTH - 1) ? nullptr : paf;
        launch_gemm(dim3(4, 64), pgf, wf + WOFF_W2, b2 + (size_t)lyr * DIMM,
                    px, outp, oh, nullptr, nullptr, NTOK, DIMM, FFPAD, DIMM, 0);
    }
}

// round 17
// speedup vs baseline: 1.0735x; 1.0735x over previous
#include <cuda_runtime.h>
#include <cuda_bf16.h>
#include <cuda_fp16.h>
#include <cstdint>
#include <cfloat>
#include <math.h>

#define NTOK 8192
#define DIMM 512
#define DEPTH 6
#define HEADS 8
#define DH 64
#define WSZ 256
#define INNER 512
#define FF 1365
#define FF2 2730
#define FFPAD 1408
#define FF2SCR 2816

// per-layer weight buffer layout (elements)
#define WOFF_QKV 0
#define WOFF_WO  786432            // 1536*512
#define WOFF_W1  1048576           // + 512*512
#define WOFF_W2  2490368           // + 2816*512
#define WLSTRIDE 3211264           // + 512*1408

// ---------------------------------------------------------------------------
// Scratch (device globals; allocation is banned)
// ---------------------------------------------------------------------------
__device__ __align__(256) float g_x[NTOK * DIMM];
__device__ __align__(256) float g_pb1[DEPTH * FF2SCR];
__device__ __align__(256) float4 g_rot[NTOK * 32];      // {c*xs, s*xs, c/xs, s/xs}
__device__ __align__(256) __half g_af[NTOK * 512];
__device__ __align__(256) __half g_a2f[NTOK * 512];
__device__ __align__(256) __half g_gf[(size_t)NTOK * FFPAD];
__device__ __align__(256) __half g_wbf[(size_t)DEPTH * WLSTRIDE];
__device__ __align__(256) __nv_bfloat16 g_qh[NTOK * 512], g_ql[NTOK * 512];
__device__ __align__(256) __nv_bfloat16 g_kh[NTOK * 512], g_kl[NTOK * 512];
__device__ __align__(256) __half g_vtf[512 * NTOK];     // v [hd][tok] fp16

__device__ __forceinline__ uint32_t smem_to_u32(const void* p) {
    uint32_t a;
    asm("{ .reg .u64 t; cvta.to.shared.u64 t, %1; cvt.u32.u64 %0, t; }" : "=r"(a) : "l"(p));
    return a;
}
__device__ __forceinline__ void cpasync16(uint32_t dst, const void* src) {
    asm volatile("cp.async.cg.shared.global [%0], [%1], 16;" :: "r"(dst), "l"(src) : "memory");
}
#define CP_COMMIT() asm volatile("cp.async.commit_group;" ::: "memory")
#define CP_WAIT(n) asm volatile("cp.async.wait_group %0;" :: "n"(n) : "memory")
#define GRID_DEP_SYNC() asm volatile("griddepcontrol.wait;" ::: "memory")
#define GRID_DEP_TRIGGER() asm volatile("griddepcontrol.launch_dependents;" ::: "memory")

__device__ __forceinline__ uint32_t swz(int r, int chunk) {
    int pr = r >> 1;
    int cc = ((r & 1) << 2) | chunk;
    cc ^= (pr & 7);
    return (uint32_t)(pr * 128 + cc * 16);
}
__device__ __forceinline__ uint32_t swz64(int r, int c) {
    return (uint32_t)(r * 128 + ((c ^ (r & 7)) * 16));
}

__device__ __forceinline__ void ldx4(uint32_t& d0, uint32_t& d1, uint32_t& d2, uint32_t& d3,
                                     uint32_t addr) {
    asm volatile("ldmatrix.sync.aligned.m8n8.x4.shared.b16 {%0,%1,%2,%3}, [%4];"
                 : "=r"(d0), "=r"(d1), "=r"(d2), "=r"(d3) : "r"(addr));
}
__device__ __forceinline__ void mma16816(float* c, uint32_t a0, uint32_t a1, uint32_t a2,
                                         uint32_t a3, uint32_t b0, uint32_t b1) {
    asm volatile(
        "mma.sync.aligned.m16n8k16.row.col.f32.bf16.bf16.f32 "
        "{%0,%1,%2,%3}, {%4,%5,%6,%7}, {%8,%9}, {%0,%1,%2,%3};"
        : "+f"(c[0]), "+f"(c[1]), "+f"(c[2]), "+f"(c[3])
        : "r"(a0), "r"(a1), "r"(a2), "r"(a3), "r"(b0), "r"(b1));
}
__device__ __forceinline__ void mma16816h(float* c, uint32_t a0, uint32_t a1, uint32_t a2,
                                          uint32_t a3, uint32_t b0, uint32_t b1) {
    asm volatile(
        "mma.sync.aligned.m16n8k16.row.col.f32.f16.f16.f32 "
        "{%0,%1,%2,%3}, {%4,%5,%6,%7}, {%8,%9}, {%0,%1,%2,%3};"
        : "+f"(c[0]), "+f"(c[1]), "+f"(c[2]), "+f"(c[3])
        : "r"(a0), "r"(a1), "r"(a2), "r"(a3), "r"(b0), "r"(b1));
}
__device__ __forceinline__ uint32_t packh2(float a, float b) {
    __half2 h = __floats2half2_rn(a, b);
    return *reinterpret_cast<uint32_t*>(&h);
}

// ===========================================================================
// One-time rotary/xpos coefficient table: (pos, d<32) -> 4 floats.
// ===========================================================================
__global__ void rot_table_kernel()
{
    int idx = blockIdx.x * 256 + threadIdx.x;
    if (idx >= NTOK * 32) return;
    int pos = idx >> 5, d = idx & 31;
    float inv_freq = powf(10000.f, -(float)d / 32.f);
    float fr = (float)pos * inv_freq;
    float c = cosf(fr), s = sinf(fr);
    float sv = (2.f * (float)d + 0.4f * 64.f) / (1.4f * 64.f);
    float pw = ((float)pos - (float)(NTOK / 2)) / (float)(WSZ / 2);
    float xs = powf(sv, pw);
    g_rot[idx] = make_float4(c * xs, s * xs, c / xs, s / xs);
}

// ===========================================================================
// Conversion kernels
// ===========================================================================
__global__ void cvt_pad_A(const float* __restrict__ src, __half* __restrict__ h,
                          int Mr, int Kc, int Kp)
{
    int idx = blockIdx.x * 256 + threadIdx.x;
    if (idx >= Mr * Kp) return;
    int r = idx / Kp, c = idx - r * Kp;
    float v = (c < Kc) ? src[(size_t)r * Kc + c] : 0.f;
    h[idx] = __float2half_rn(v);
}

__global__ void cvt_pad_Bt(const float* __restrict__ src, __half* __restrict__ h,
                           int Kc, int Nc, int Kp, int Nscr, int srcStride, int gluPerm)
{
    __shared__ float t[32][33];
    int tk0 = blockIdx.x * 32;
    int tn0 = blockIdx.y * 32;
    int tx = threadIdx.x & 31;
    int ty = threadIdx.x >> 5;

    int nout = tn0 + tx;
    int ns; bool nok;
    if (gluPerm) {
        int p = nout >> 1;
        ns = (nout & 1) ? p + FF : p;
        nok = p < FF;
    } else {
        ns = nout;
        nok = nout < Nc;
    }
#pragma unroll
    for (int i = 0; i < 4; i++) {
        int k = tk0 + ty + 8 * i;
        float v = (k < Kc && nok) ? src[(size_t)k * srcStride + ns] : 0.f;
        t[ty + 8 * i][tx] = v;
    }
    __syncthreads();
#pragma unroll
    for (int i = 0; i < 4; i++) {
        int n = tn0 + ty + 8 * i, k = tk0 + tx;
        if (n < Nscr && k < Kp)
            h[(size_t)n * Kp + k] = __float2half_rn(t[tx][ty + 8 * i]);
    }
}

__global__ void permute_b1_kernel(const float* __restrict__ b1, float* __restrict__ dst)
{
    int n = blockIdx.x * 256 + threadIdx.x;
    if (n >= FF2SCR) return;
    int p = n >> 1;
    dst[n] = (p < FF) ? b1[(n & 1) ? p + FF : p] : 0.f;
}

// ===========================================================================
// fp16 single-term tensor-core GEMM with PDL, BK=32, 4-stage pipeline with
// issue-before-wait (stage it+2 mod 4 was last read at it-2; safe after the
// barrier of it-1).
// mode 0: fp32 C (+bias,+res) and optional fp16 plane Oh.
// mode 1: GLU epilogue -> fp16 plane Oh.
// mode 2: QKV epilogue -> qknorm+rotary -> g_qh/ql/kh/kl; v -> g_vtf.
// ===========================================================================
#define STAGE_BYTES 16384
#define NSTAGE 4
#define GEMM_SMEM (NSTAGE * STAGE_BYTES + 1024)

__global__ void __launch_bounds__(256, 2) fp16_gemm_kernel(
    const __half* __restrict__ A, const __half* __restrict__ B,
    const float* __restrict__ bias, const float* __restrict__ res,
    float* __restrict__ C, __half* __restrict__ Oh,
    const float* __restrict__ qsc, const float* __restrict__ ksc,
    int M, int N, int Kpad, int ostride, int mode)
{
    extern __shared__ char smraw[];
    char* sm = (char*)(((uintptr_t)smraw + 1023) & ~(uintptr_t)1023);
    uint32_t sb = smem_to_u32(sm);

    int tid = threadIdx.x, wid = tid >> 5, lane = tid & 31;
    int mw = wid >> 1, nw = wid & 1;
    int m0 = blockIdx.y * 128, n0 = blockIdx.x * 128;

    uint32_t aAddr[2], bAddr[4];
    {
        int t = lane >> 3, l7 = lane & 7;
#pragma unroll
        for (int mi = 0; mi < 2; mi++) {
            int r = mw * 32 + mi * 16 + ((t & 1) << 3) + l7;
            aAddr[mi] = sb + swz(r, t >> 1);
        }
#pragma unroll
        for (int j = 0; j < 4; j++) {
            int r = nw * 64 + j * 16 + ((t >> 1) << 3) + l7;
            bAddr[j] = sb + 8192 + swz(r, t & 1);
        }
    }

    float acc[2][8][4];
#pragma unroll
    for (int mi = 0; mi < 2; mi++)
#pragma unroll
        for (int j = 0; j < 8; j++)
#pragma unroll
            for (int q = 0; q < 4; q++) acc[mi][j][q] = 0.f;

    const int niter = Kpad / 32;
    int cr = tid >> 1;
    int c0 = (tid & 1) * 2;
    const __half* aSrc = A + (size_t)(m0 + cr) * Kpad + c0 * 8;
    const __half* bSrc = B + (size_t)(n0 + cr) * Kpad + c0 * 8;
    uint32_t dA0 = swz(cr, c0), dA1 = swz(cr, c0 + 1);

#define ISSUE_STAGE(s, k0) do {                                           \
        uint32_t base = sb + (uint32_t)(s) * STAGE_BYTES;                 \
        cpasync16(base + dA0,        aSrc + (k0));                        \
        cpasync16(base + dA1,        aSrc + (k0) + 8);                    \
        cpasync16(base + 8192 + dA0, bSrc + (k0));                        \
        cpasync16(base + 8192 + dA1, bSrc + (k0) + 8);                    \
        CP_COMMIT();                                                      \
    } while (0)

    // ---- PDL prologue: B (weights) for stages 0,1 are predecessor-independent
    cpasync16(sb + 8192 + dA0, bSrc);
    cpasync16(sb + 8192 + dA1, bSrc + 8);
    cpasync16(sb + STAGE_BYTES + 8192 + dA0, bSrc + 32);
    cpasync16(sb + STAGE_BYTES + 8192 + dA1, bSrc + 40);
    GRID_DEP_SYNC();                 // wait for predecessor's output (A side)
    cpasync16(sb + dA0, aSrc);
    cpasync16(sb + dA1, aSrc + 8);
    CP_COMMIT();                     // G1 = {B s0, B s1, A s0}
    cpasync16(sb + STAGE_BYTES + dA0, aSrc + 32);
    cpasync16(sb + STAGE_BYTES + dA1, aSrc + 40);
    CP_COMMIT();                     // G2 = {A s1}

    for (int it = 0; it < niter; ++it) {
        int s = it % NSTAGE;
        // issue-before-wait: stage (it+2)%4 was last read at it-2 (all warps
        // finished those reads before the barrier at it-1).
        if (it + 2 < niter) {
            ISSUE_STAGE((it + 2) % NSTAGE, (it + 2) * 32);
            CP_WAIT(2);
        } else if (it + 1 < niter) {
            CP_WAIT(1);
        } else {
            CP_WAIT(0);
        }
        __syncthreads();

        uint32_t stage = (uint32_t)s * STAGE_BYTES;
#pragma unroll
        for (int kk = 0; kk < 2; kk++) {
            uint32_t x = (uint32_t)(kk * 32);
            uint32_t ah[2][4], bh[4][4];
            ldx4(ah[0][0], ah[0][1], ah[0][2], ah[0][3], (aAddr[0] + stage) ^ x);
            ldx4(ah[1][0], ah[1][1], ah[1][2], ah[1][3], (aAddr[1] + stage) ^ x);
#pragma unroll
            for (int j = 0; j < 4; j++)
                ldx4(bh[j][0], bh[j][1], bh[j][2], bh[j][3], (bAddr[j] + stage) ^ x);
#pragma unroll
            for (int mi = 0; mi < 2; mi++)
#pragma unroll
                for (int j = 0; j < 4; j++) {
                    mma16816h(acc[mi][2 * j],     ah[mi][0], ah[mi][1], ah[mi][2], ah[mi][3], bh[j][0], bh[j][1]);
                    mma16816h(acc[mi][2 * j + 1], ah[mi][0], ah[mi][1], ah[mi][2], ah[mi][3], bh[j][2], bh[j][3]);
                }
        }
    }
#undef ISSUE_STAGE

    GRID_DEP_TRIGGER();              // successors may launch & prefetch weights

    int colq = (lane & 3) * 2;

    if (mode == 2) {
        int colbase = n0 + nw * 64;          // one head-segment per warp-half
        int region = n0 >> 9;                // CTA-uniform: 0=q, 1=k, 2=v
        if (region == 2) {
            // ---- V: transpose via smem stage, coalesced write to g_vtf ----
            __half* vs = (__half*)sm;        // [128 dims][136 toks] padded
            __syncthreads();                 // all warps done reading pipeline smem
#pragma unroll
            for (int mi = 0; mi < 2; mi++) {
#pragma unroll
                for (int half = 0; half < 2; half++) {
                    int rloc = mw * 32 + mi * 16 + (lane >> 2) + half * 8;  // token
#pragma unroll
                    for (int j = 0; j < 8; j++) {
                        int cloc = nw * 64 + j * 8 + colq;                  // v-dim
                        vs[(size_t)cloc * 136 + rloc] = __float2half_rn(acc[mi][j][half * 2]);
                        vs[(size_t)(cloc + 1) * 136 + rloc] = __float2half_rn(acc[mi][j][half * 2 + 1]);
                    }
                }
            }
            __syncthreads();
            int hdl = tid >> 1;              // local dim row 0..127
            int tk0 = (tid & 1) * 64;        // token half
            __half* dst = g_vtf + (size_t)(n0 - 1024 + hdl) * NTOK + m0 + tk0;
            const __half* srcp = vs + (size_t)hdl * 136 + tk0;
#pragma unroll
            for (int i = 0; i < 8; i++)
                *(uint4*)(dst + i * 8) = *(const uint4*)(srcp + i * 8);
            return;
        }
        // ---- Q/K: qknorm + xpos rotary fused ----
#pragma unroll
        for (int mi = 0; mi < 2; mi++) {
#pragma unroll
            for (int half = 0; half < 2; half++) {
                int r = m0 + mw * 32 + mi * 16 + (lane >> 2) + half * 8;
                float ss = 0.f;
#pragma unroll
                for (int j = 0; j < 8; j++) {
                    float a = acc[mi][j][half * 2], b = acc[mi][j][half * 2 + 1];
                    ss += a * a + b * b;
                }
                ss += __shfl_xor_sync(0xFFFFFFFF, ss, 1);
                ss += __shfl_xor_sync(0xFFFFFFFF, ss, 2);
                float invn = 1.f / fmaxf(sqrtf(ss), 1e-12f);
                const float* sc = (region == 0) ? qsc : ksc;
                __nv_bfloat16* OH = (region == 0) ? g_qh : g_kh;
                __nv_bfloat16* OL = (region == 0) ? g_ql : g_kl;
                int cb = colbase - region * 512;
#pragma unroll
                for (int j = 0; j < 4; j++) {
                    int d0 = j * 8 + colq;
                    float4 t0 = g_rot[(size_t)r * 32 + d0];
                    float4 t1 = g_rot[(size_t)r * 32 + d0 + 1];
                    float cx0 = (region == 0) ? t0.x : t0.z;
                    float sx0 = (region == 0) ? t0.y : t0.w;
                    float cx1 = (region == 0) ? t1.x : t1.z;
                    float sx1 = (region == 0) ? t1.y : t1.w;
                    float v00 = acc[mi][j][half * 2]         * invn * sc[d0];
                    float v01 = acc[mi][j][half * 2 + 1]     * invn * sc[d0 + 1];
                    float w00 = acc[mi][j + 4][half * 2]     * invn * sc[d0 + 32];
                    float w01 = acc[mi][j + 4][half * 2 + 1] * invn * sc[d0 + 33];
                    float oA0 = v00 * cx0 - w00 * sx0;
                    float oA1 = v01 * cx1 - w01 * sx1;
                    float oB0 = w00 * cx0 + v00 * sx0;
                    float oB1 = w01 * cx1 + v01 * sx1;
                    size_t o1 = (size_t)r * 512 + cb + j * 8 + colq;
                    size_t o2 = o1 + 32;
                    __nv_bfloat162 h0 = __floats2bfloat162_rn(oA0, oA1);
                    float2 f0 = __bfloat1622float2(h0);
                    *(__nv_bfloat162*)(OH + o1) = h0;
                    *(__nv_bfloat162*)(OL + o1) = __floats2bfloat162_rn(oA0 - f0.x, oA1 - f0.y);
                    __nv_bfloat162 h1 = __floats2bfloat162_rn(oB0, oB1);
                    float2 f1 = __bfloat1622float2(h1);
                    *(__nv_bfloat162*)(OH + o2) = h1;
                    *(__nv_bfloat162*)(OL + o2) = __floats2bfloat162_rn(oB0 - f1.x, oB1 - f1.y);
                }
            }
        }
        return;
    }

#pragma unroll
    for (int mi = 0; mi < 2; mi++) {
        int rbase = m0 + mw * 32 + mi * 16 + (lane >> 2);
#pragma unroll
        for (int j = 0; j < 8; j++) {
            int col = n0 + nw * 64 + j * 8 + colq;
            if (col < N) {
                float bx = 0.f, by = 0.f;
                if (bias) { bx = bias[col]; by = bias[col + 1]; }
                if (mode == 1) {
                    int p = col >> 1;
#pragma unroll
                    for (int half = 0; half < 2; half++) {
                        int r = rbase + half * 8;
                        float a = acc[mi][j][half * 2] + bx;
                        float g = acc[mi][j][half * 2 + 1] + by;
                        float v = a * 0.5f * g * (1.f + erff(g * 0.70710678118654752f));
                        Oh[(size_t)r * ostride + p] = __float2half_rn(v);
                    }
                } else {
#pragma unroll
                    for (int half = 0; half < 2; half++) {
                        int r = rbase + half * 8;
                        size_t o = (size_t)r * N + col;
                        float v0 = acc[mi][j][half * 2] + bx;
                        float v1 = acc[mi][j][half * 2 + 1] + by;
                        if (res) { v0 += res[o]; v1 += res[o + 1]; }
                        *(float2*)(C + o) = make_float2(v0, v1);
                        if (Oh) {
                            __half2 hv = __floats2half2_rn(v0, v1);
                            *(__half2*)(Oh + (size_t)r * ostride + col) = hv;
                        }
                    }
                }
            }
        }
    }
}

// ===========================================================================
// Tensor-core flash attention (R12 validated) with PDL wrap.
// ===========================================================================
#define ATT_STAGE 24576
#define ATT_SMEM (32768 + 2 * ATT_STAGE + 1024)

__global__ void __launch_bounds__(256) flash_attn_kernel()
{
    extern __shared__ char smraw[];
    char* sm = (char*)(((uintptr_t)smraw + 1023) & ~(uintptr_t)1023);
    uint32_t sb = smem_to_u32(sm);

    int tid = threadIdx.x, wid = tid >> 5, lane = tid & 31;
    int qb = blockIdx.x;
    int h = blockIdx.y;
    int start = (qb - 2) * 128;
    int cBeg = (start < 0) ? (-start) / 64 : 0;

    GRID_DEP_SYNC();   // all loads depend on the QKV GEMM's output

#define LOAD_CHUNK(sidx, kb_) do {                                                     \
        uint32_t base_ = sb + 32768 + (uint32_t)(sidx) * ATT_STAGE;                    \
        _Pragma("unroll")                                                              \
        for (int i_ = 0; i_ < 2; i_++) {                                               \
            int slot_ = tid * 2 + i_;                                                  \
            int row_ = slot_ >> 3, ch_ = slot_ & 7;                                    \
            uint32_t d_ = swz64(row_, ch_);                                            \
            cpasync16(base_ + d_,         g_kh + (size_t)((kb_) + row_) * 512 + h * 64 + ch_ * 8); \
            cpasync16(base_ + 8192 + d_,  g_kl + (size_t)((kb_) + row_) * 512 + h * 64 + ch_ * 8); \
            cpasync16(base_ + 16384 + d_, g_vtf + (size_t)(h * 64 + row_) * NTOK + (kb_) + ch_ * 8); \
        }                                                                              \
        CP_COMMIT();                                                                   \
    } while (0)

    {
#pragma unroll
        for (int i = 0; i < 4; i++) {
            int slot = tid * 4 + i;
            int row = slot >> 3, ch = slot & 7;
            uint32_t d = swz64(row, ch);
            const __nv_bfloat16* sh = g_qh + (size_t)(qb * 128 + row) * 512 + h * 64 + ch * 8;
            const __nv_bfloat16* slo = g_ql + (size_t)(qb * 128 + row) * 512 + h * 64 + ch * 8;
            cpasync16(sb + d, sh);
            cpasync16(sb + 16384 + d, slo);
        }
        LOAD_CHUNK(0, start + cBeg * 64);
        if (cBeg + 1 <= 5) LOAD_CHUNK(1, start + (cBeg + 1) * 64);
    }

    int t = lane >> 3, l7 = lane & 7;
    uint32_t aOff = swz64(wid * 16 + ((t & 1) << 3) + l7, t >> 1);
    uint32_t bOff[4];
#pragma unroll
    for (int j = 0; j < 4; j++)
        bOff[j] = swz64(j * 16 + ((t >> 1) << 3) + l7, t & 1);

    uint32_t qfh[4][4], qfl[4][4];
    float o4[8][4];
#pragma unroll
    for (int j = 0; j < 8; j++)
#pragma unroll
        for (int q = 0; q < 4; q++) o4[j][q] = 0.f;
    float m0 = -16.f, m1 = -16.f, l0 = 0.f, l1 = 0.f;

    int r0 = qb * 128 + wid * 16 + (lane >> 2);
    int colq = (lane & 3) * 2;
    int tqmin = qb * 128 + wid * 16;

    for (int c = cBeg; c <= 5; c++) {
        int s = (c - cBeg) & 1;
        int kb = start + c * 64;
        if (c < 5) CP_WAIT(1); else CP_WAIT(0);
        __syncthreads();

        if (c == cBeg) {
#pragma unroll
            for (int ks = 0; ks < 4; ks++) {
                uint32_t x = (uint32_t)(ks * 32);
                ldx4(qfh[ks][0], qfh[ks][1], qfh[ks][2], qfh[ks][3], (sb + aOff) ^ x);
                ldx4(qfl[ks][0], qfl[ks][1], qfl[ks][2], qfl[ks][3], (sb + 16384 + aOff) ^ x);
            }
        }

        bool active = ((tqmin + 15 - kb) >= 0) && ((tqmin - (kb + 63)) <= WSZ);
        if (active) {
            uint32_t kvb = sb + 32768 + (uint32_t)s * ATT_STAGE;

            float s4[8][4];
#pragma unroll
            for (int j = 0; j < 8; j++)
#pragma unroll
                for (int q = 0; q < 4; q++) s4[j][q] = 0.f;

#pragma unroll
            for (int ks = 0; ks < 4; ks++) {
                uint32_t x = (uint32_t)(ks * 32);
                uint32_t bh[4][4], bl[4][4];
#pragma unroll
                for (int j = 0; j < 4; j++) {
                    ldx4(bh[j][0], bh[j][1], bh[j][2], bh[j][3], (kvb + bOff[j]) ^ x);
                    ldx4(bl[j][0], bl[j][1], bl[j][2], bl[j][3], (kvb + 8192 + bOff[j]) ^ x);
                }
#pragma unroll
                for (int j = 0; j < 4; j++) {
                    mma16816(s4[2 * j],     qfh[ks][0], qfh[ks][1], qfh[ks][2], qfh[ks][3], bh[j][0], bh[j][1]);
                    mma16816(s4[2 * j + 1], qfh[ks][0], qfh[ks][1], qfh[ks][2], qfh[ks][3], bh[j][2], bh[j][3]);
                    mma16816(s4[2 * j],     qfh[ks][0], qfh[ks][1], qfh[ks][2], qfh[ks][3], bl[j][0], bl[j][1]);
                    mma16816(s4[2 * j + 1], qfh[ks][0], qfh[ks][1], qfh[ks][2], qfh[ks][3], bl[j][2], bl[j][3]);
                    mma16816(s4[2 * j],     qfl[ks][0], qfl[ks][1], qfl[ks][2], qfl[ks][3], bh[j][0], bh[j][1]);
                    mma16816(s4[2 * j + 1], qfl[ks][0], qfl[ks][1], qfl[ks][2], qfl[ks][3], bh[j][2], bh[j][3]);
                }
            }

#pragma unroll
            for (int j = 0; j < 8; j++) {
                int tkb = kb + j * 8 + colq;
#pragma unroll
                for (int q = 0; q < 4; q++) {
                    int tq = r0 + ((q >> 1) << 3);
                    int tk = tkb + (q & 1);
                    int diff = tq - tk;
                    s4[j][q] = (diff >= 0 && diff <= WSZ) ? s4[j][q] * 8.0f : -1e30f;
                }
            }
            float mx0 = -1e30f, mx1 = -1e30f;
#pragma unroll
            for (int j = 0; j < 8; j++) {
                mx0 = fmaxf(mx0, fmaxf(s4[j][0], s4[j][1]));
                mx1 = fmaxf(mx1, fmaxf(s4[j][2], s4[j][3]));
            }
            mx0 = fmaxf(mx0, __shfl_xor_sync(0xFFFFFFFF, mx0, 1));
            mx0 = fmaxf(mx0, __shfl_xor_sync(0xFFFFFFFF, mx0, 2));
            mx1 = fmaxf(mx1, __shfl_xor_sync(0xFFFFFFFF, mx1, 1));
            mx1 = fmaxf(mx1, __shfl_xor_sync(0xFFFFFFFF, mx1, 2));
            float mn0 = fmaxf(m0, mx0), mn1 = fmaxf(m1, mx1);
            float sc0 = __expf(m0 - mn0), sc1 = __expf(m1 - mn1);
            l0 *= sc0; l1 *= sc1;
#pragma unroll
            for (int j = 0; j < 8; j++) {
                o4[j][0] *= sc0; o4[j][1] *= sc0;
                o4[j][2] *= sc1; o4[j][3] *= sc1;
            }
            m0 = mn0; m1 = mn1;
#pragma unroll
            for (int j = 0; j < 8; j++) {
                float p0 = __expf(s4[j][0] - m0);
                float p1 = __expf(s4[j][1] - m0);
                float p2 = __expf(s4[j][2] - m1);
                float p3 = __expf(s4[j][3] - m1);
                l0 += p0 + p1; l1 += p2 + p3;
                s4[j][0] = p0; s4[j][1] = p1; s4[j][2] = p2; s4[j][3] = p3;
            }
            uint32_t pf[4][4];
#pragma unroll
            for (int ks = 0; ks < 4; ks++) {
                pf[ks][0] = packh2(s4[2 * ks][0],     s4[2 * ks][1]);
                pf[ks][1] = packh2(s4[2 * ks][2],     s4[2 * ks][3]);
                pf[ks][2] = packh2(s4[2 * ks + 1][0], s4[2 * ks + 1][1]);
                pf[ks][3] = packh2(s4[2 * ks + 1][2], s4[2 * ks + 1][3]);
            }
#pragma unroll
            for (int ks = 0; ks < 4; ks++) {
                uint32_t x = (uint32_t)(ks * 32);
                uint32_t vf[4][4];
#pragma unroll
                for (int j = 0; j < 4; j++)
                    ldx4(vf[j][0], vf[j][1], vf[j][2], vf[j][3], (kvb + 16384 + bOff[j]) ^ x);
#pragma unroll
                for (int j = 0; j < 4; j++) {
                    mma16816h(o4[2 * j],     pf[ks][0], pf[ks][1], pf[ks][2], pf[ks][3], vf[j][0], vf[j][1]);
                    mma16816h(o4[2 * j + 1], pf[ks][0], pf[ks][1], pf[ks][2], pf[ks][3], vf[j][2], vf[j][3]);
                }
            }
        }

        __syncthreads();
        if (c + 2 <= 5) LOAD_CHUNK(s, start + (c + 2) * 64);
    }
#undef LOAD_CHUNK

    GRID_DEP_TRIGGER();

    l0 += __shfl_xor_sync(0xFFFFFFFF, l0, 1);
    l0 += __shfl_xor_sync(0xFFFFFFFF, l0, 2);
    l1 += __shfl_xor_sync(0xFFFFFFFF, l1, 1);
    l1 += __shfl_xor_sync(0xFFFFFFFF, l1, 2);
    float il0 = 1.f / l0, il1 = 1.f / l1;

#pragma unroll
    for (int j = 0; j < 8; j++) {
        int col = h * 64 + j * 8 + colq;
        size_t off0 = (size_t)r0 * 512 + col;
        size_t off1 = (size_t)(r0 + 8) * 512 + col;
        *(__half2*)(g_af + off0) = __floats2half2_rn(o4[j][0] * il0, o4[j][1] * il0);
        *(__half2*)(g_af + off1) = __floats2half2_rn(o4[j][2] * il1, o4[j][3] * il1);
    }
}

// ---------------------------------------------------------------------------
extern "C" void kernel_launch(void* const* d_in, const int* in_sizes, int n_in,
                              void* d_out, int out_size)
{
    const float* x      = (const float*)d_in[0];
    const float* Wqkv   = (const float*)d_in[1];
    const float* Wo     = (const float*)d_in[2];
    const float* qscale = (const float*)d_in[3];
    const float* kscale = (const float*)d_in[4];
    const float* W1     = (const float*)d_in[5];
    const float* b1     = (const float*)d_in[6];
    const float* W2     = (const float*)d_in[7];
    const float* b2     = (const float*)d_in[8];

    float *px, *ppb1;
    __half *paf, *pa2f, *pgf, *pwbf;
    cudaGetSymbolAddress((void**)&px, g_x);
    cudaGetSymbolAddress((void**)&ppb1, g_pb1);
    cudaGetSymbolAddress((void**)&paf, g_af);
    cudaGetSymbolAddress((void**)&pa2f, g_a2f);
    cudaGetSymbolAddress((void**)&pgf, g_gf);
    cudaGetSymbolAddress((void**)&pwbf, g_wbf);

    cudaFuncSetAttribute(fp16_gemm_kernel,
                         cudaFuncAttributeMaxDynamicSharedMemorySize, GEMM_SMEM);
    cudaFuncSetAttribute(flash_attn_kernel,
                         cudaFuncAttributeMaxDynamicSharedMemorySize, ATT_SMEM);

    cudaStream_t s1;
    cudaStreamCreateWithFlags(&s1, cudaStreamNonBlocking);
    cudaEvent_t evFork, evWq[DEPTH], evW[DEPTH];
    cudaEventCreateWithFlags(&evFork, cudaEventDisableTiming);
    for (int l = 0; l < DEPTH; l++) {
        cudaEventCreateWithFlags(&evWq[l], cudaEventDisableTiming);
        cudaEventCreateWithFlags(&evW[l], cudaEventDisableTiming);
    }
    cudaEventRecord(evFork, 0);
    cudaStreamWaitEvent(s1, evFork, 0);

    // all layers' weight conversions upfront on the side stream
    for (int l = 0; l < DEPTH; l++) {
        __half* wf = pwbf + (size_t)l * WLSTRIDE;
        cvt_pad_Bt<<<dim3(16, 48), 256, 0, s1>>>(
            Wqkv + (size_t)l * DIMM * 3 * INNER, wf + WOFF_QKV,
            DIMM, 3 * INNER, 512, 1536, 3 * INNER, 0);
        cudaEventRecord(evWq[l], s1);
        cvt_pad_Bt<<<dim3(16, 16), 256, 0, s1>>>(
            Wo + (size_t)l * INNER * DIMM, wf + WOFF_WO,
            INNER, DIMM, 512, 512, DIMM, 0);
        cvt_pad_Bt<<<dim3(16, 88), 256, 0, s1>>>(
            W1 + (size_t)l * DIMM * FF2, wf + WOFF_W1,
            DIMM, FF2SCR, 512, FF2SCR, FF2, 1);
        permute_b1_kernel<<<(FF2SCR + 255) / 256, 256, 0, s1>>>(
            b1 + (size_t)l * FF2, ppb1 + (size_t)l * FF2SCR);
        cvt_pad_Bt<<<dim3(44, 16), 256, 0, s1>>>(
            W2 + (size_t)l * FF * DIMM, wf + WOFF_W2,
            FF, DIMM, FFPAD, 512, DIMM, 0);
        cudaEventRecord(evW[l], s1);
    }

    rot_table_kernel<<<(NTOK * 32 + 255) / 256, 256>>>();
    cvt_pad_A<<<(NTOK * 512 + 255) / 256, 256>>>(x, paf, NTOK, DIMM, 512);

    // PDL launch helpers
    cudaLaunchAttribute pdlAttr[1];
    pdlAttr[0].id = cudaLaunchAttributeProgrammaticStreamSerialization;
    pdlAttr[0].val.programmaticStreamSerializationAllowed = 1;

    auto launch_gemm = [&](dim3 grid, const __half* A, const __half* B,
                           const float* bias, const float* res, float* C,
                           __half* Oh, const float* qsc, const float* ksc,
                           int M, int N, int Kpad, int ostride, int mode) {
        cudaLaunchConfig_t cfg = {};
        cfg.gridDim = grid;
        cfg.blockDim = dim3(256, 1, 1);
        cfg.dynamicSmemBytes = GEMM_SMEM;
        cfg.stream = 0;
        cfg.attrs = pdlAttr;
        cfg.numAttrs = 1;
        cudaLaunchKernelEx(&cfg, fp16_gemm_kernel, A, B, bias, res, C, Oh,
                           qsc, ksc, M, N, Kpad, ostride, mode);
    };

    for (int lyr = 0; lyr < DEPTH; lyr++) {
        const float* xres = (lyr == 0) ? x : px;
        __half* wf = pwbf + (size_t)lyr * WLSTRIDE;

        // 1) QKV projection: fused qknorm+rotary epilogue + fused V transpose
        cudaStreamWaitEvent(0, evWq[lyr], 0);
        launch_gemm(dim3(12, 64), paf, wf + WOFF_QKV, nullptr, nullptr,
                    nullptr, nullptr, qscale + lyr * DH, kscale + lyr * DH,
                    NTOK, 3 * INNER, 512, 0, 2);

        // 2) flash attention -> g_af
        {
            cudaLaunchConfig_t cfg = {};
            cfg.gridDim = dim3(64, 8);
            cfg.blockDim = dim3(256, 1, 1);
            cfg.dynamicSmemBytes = ATT_SMEM;
            cfg.stream = 0;
            cfg.attrs = pdlAttr;
            cfg.numAttrs = 1;
            cudaLaunchKernelEx(&cfg, flash_attn_kernel);
        }

        // 3) output projection + residual; fp16 plane out
        cudaStreamWaitEvent(0, evW[lyr], 0);
        launch_gemm(dim3(4, 64), paf, wf + WOFF_WO, nullptr, xres,
                    px, pa2f, nullptr, nullptr, NTOK, DIMM, 512, DIMM, 0);

        // 4) FF up projection + b1 + fused GLU
        launch_gemm(dim3(22, 64), pa2f, wf + WOFF_W1,
                    ppb1 + (size_t)lyr * FF2SCR, nullptr, nullptr, pgf,
                    nullptr, nullptr, NTOK, FF2SCR, 512, FFPAD, 1);

        // 5) FF down projection + b2 + residual
        float* outp = (lyr == DEPTH - 1) ? (float*)d_out : px;
        __half* oh = (lyr == DEPTH - 1) ? nullptr : paf;
        launch_gemm(dim3(4, 64), pgf, wf + WOFF_W2, b2 + (size_t)lyr * DIMM,
                    px, outp, oh, nullptr, nullptr, NTOK, DIMM, FFPAD, DIMM, 0);
    }
}